// round 15
// baseline (speedup 1.0000x reference)
#include <cuda_runtime.h>
#include <cuda_fp16.h>
#include <cstdint>

#define N_NODES 4096
#define N_EDGES 262144
#define NFEAT   512
#define NHID    64
#define NHEAD   8
#define HTOT    512   // NHEAD*NHID
#define NCLASS  16
#define ALPHA_S 0.2f
#define ADJ_W   128   // words per bitmap row (4096/32)
#define CAPW    256   // max neighbors for precomputed-weight fast path

// ---------------- scratch (static device globals; no allocation) ------------
__device__ uint32_t g_adj[N_NODES * ADJ_W];     // 2 MB adjacency bitmap (src rows)
__device__ __half   g_Xh [N_NODES * NFEAT];     // features split hi (fp16)
__device__ __half   g_Xl [N_NODES * NFEAT];     // features split lo (fp16)
__device__ __half   g_Wh [HTOT * NFEAT];        // W1 packed+transposed [n][k], hi
__device__ __half   g_Wl [HTOT * NFEAT];        // W1 packed+transposed [n][k], lo
__device__ float    g_H1 [N_NODES * HTOT];      // layer-1 per-head features (fp32)
__device__ __half   g_H1h[N_NODES * HTOT];      // fp16 copy for the gather
__device__ float    g_X2 [N_NODES * HTOT];      // elu(agg1) = layer-2 input
__device__ float    g_H2 [N_NODES * NCLASS];    // layer-2 projected features
__device__ float    g_s1s[N_NODES * NHEAD];     // layer-1 src scores
__device__ float    g_s1t[N_NODES * NHEAD];     // layer-1 tgt scores
__device__ float    g_s2s[N_NODES];
__device__ float    g_s2t[N_NODES];
__device__ int      g_is64;

// Detect int64 vs int32 edge buffer: int64 little-endian values <4096 have all
// odd 32-bit words == 0; int32 odd words are random node ids (P(all 0) ~ 0).
__global__ void k_detect(const uint32_t* __restrict__ el) {
    uint32_t acc = 0;
#pragma unroll
    for (int i = 1; i < 256; i += 2) acc |= el[i];
    g_is64 = (acc == 0u) ? 1 : 0;
}

__global__ void k_scatter(const void* __restrict__ elv) {
    int e = blockIdx.x * blockDim.x + threadIdx.x;
    if (e >= N_EDGES) return;
    int src, tgt;
    if (g_is64) {
        const long long* el = (const long long*)elv;
        src = (int)el[e]; tgt = (int)el[N_EDGES + e];
    } else {
        const int* el = (const int*)elv;
        src = el[e]; tgt = el[N_EDGES + e];
    }
    src &= (N_NODES - 1); tgt &= (N_NODES - 1);
    atomicOr(&g_adj[src * ADJ_W + (tgt >> 5)], 1u << (tgt & 31));
}

// ---------------- prep: coalesced W pack/transpose + X hi/lo split ----------
// blocks [0,256): W_heads [8,512,64] -> g_W{h,l}[n=512][k=512] via 32x32 tiles
// blocks [256,1280): split features (2M elems, 2 per thread)
__global__ void __launch_bounds__(1024) k_prep(const float* __restrict__ X,
                                               const float* __restrict__ W) {
    int b = blockIdx.x;
    if (b < 256) {
        __shared__ float t[32][33];
        int h  = b >> 5;
        int kt = (b >> 1) & 15;
        int ft = b & 1;
        int tx = threadIdx.x & 31, ty = threadIdx.x >> 5;
        t[ty][tx] = W[h * (NFEAT * NHID) + (kt * 32 + ty) * NHID + ft * 32 + tx];
        __syncthreads();
        float w = t[tx][ty];
        __half hi = __float2half_rn(w);
        __half lo = __float2half_rn(w - __half2float(hi));
        int o = (h * 64 + ft * 32 + ty) * NFEAT + kt * 32 + tx;
        g_Wh[o] = hi;
        g_Wl[o] = lo;
    } else {
        int i = (b - 256) * 2048 + threadIdx.x;
#pragma unroll
        for (int u = 0; u < 2; u++, i += 1024) {
            float x = X[i];
            __half hi = __float2half_rn(x);
            g_Xh[i] = hi;
            g_Xl[i] = __float2half_rn(x - __half2float(hi));
        }
    }
}

// ---------------- GEMM1 on tensor cores (split-fp16, fp32-exact) ------------
// C = Ah@Bh + Ah@Bl + Al@Bh.  BM=128, BN=128, BK=32, 2-stage cp.async pipeline,
// ldmatrix.x4 fragment loads. 8 warps (4m x 2n), warp tile 32x64, mma.m16n8k16.
// Epilogue also computes the per-(row,head) score halves (fused k_score1).
#define LDT   40       // smem row stride in halves (32 + 8 pad)
#define TILEH (128 * LDT)

#define MMA16816(d, a0, a1, a2, a3, b0, b1)                                   \
    asm volatile(                                                             \
        "mma.sync.aligned.m16n8k16.row.col.f32.f16.f16.f32 "                  \
        "{%0,%1,%2,%3}, {%4,%5,%6,%7}, {%8,%9}, {%0,%1,%2,%3};"               \
        : "+f"(d[0]), "+f"(d[1]), "+f"(d[2]), "+f"(d[3])                      \
        : "r"(a0), "r"(a1), "r"(a2), "r"(a3), "r"(b0), "r"(b1))

#define LDSM4(r, addr)                                                        \
    asm volatile("ldmatrix.sync.aligned.m8n8.x4.shared.b16 {%0,%1,%2,%3}, [%4];" \
                 : "=r"((r)[0]), "=r"((r)[1]), "=r"((r)[2]), "=r"((r)[3])     \
                 : "r"(addr))

#define CPA16(smemaddr, gptr)                                                 \
    asm volatile("cp.async.ca.shared.global [%0], [%1], 16;"                  \
                 :: "r"(smemaddr), "l"(gptr) : "memory")

__global__ void __launch_bounds__(256) k_gemm1_tc(const float* __restrict__ a_heads) {
    extern __shared__ __half sm[];
    __half* SA_h = sm;                 // [2][TILEH]
    __half* SA_l = sm + 2 * TILEH;
    __half* SB_h = sm + 4 * TILEH;
    __half* SB_l = sm + 6 * TILEH;

    const int tid  = threadIdx.x;
    const int lane = tid & 31;
    const int warp = tid >> 5;
    const int wm   = warp >> 1;           // 0..3
    const int wn   = warp & 1;            // 0..1
    const int bm   = blockIdx.y * 128;
    const int bn   = blockIdx.x * 128;
    const int g    = lane >> 2;           // 0..7
    const int tg   = lane & 3;            // 0..3

    float acc[2][8][4];
#pragma unroll
    for (int i = 0; i < 2; i++)
#pragma unroll
        for (int j = 0; j < 8; j++)
#pragma unroll
            for (int k = 0; k < 4; k++) acc[i][j][k] = 0.f;

    // per-lane ldmatrix base addresses (bytes): row = base + (lane&15),
    // col = (lane>>4)*8 halves
    const int lrow = lane & 15;
    const int lcol = (lane >> 4) * 8;
    const uint32_t aAh = (uint32_t)__cvta_generic_to_shared(SA_h) +
                         (uint32_t)(((wm * 32 + lrow) * LDT + lcol) * 2);
    const uint32_t aAl = (uint32_t)__cvta_generic_to_shared(SA_l) +
                         (uint32_t)(((wm * 32 + lrow) * LDT + lcol) * 2);
    const uint32_t aBh = (uint32_t)__cvta_generic_to_shared(SB_h) +
                         (uint32_t)(((wn * 64 + lrow) * LDT + lcol) * 2);
    const uint32_t aBl = (uint32_t)__cvta_generic_to_shared(SB_l) +
                         (uint32_t)(((wn * 64 + lrow) * LDT + lcol) * 2);

#define LOAD_STAGE(st, k0)                                                        \
    do {                                                                          \
        _Pragma("unroll")                                                         \
        for (int u = 0; u < 2; u++) {                                             \
            int idx = tid * 2 + u;                                                \
            int rr = idx >> 2, cc = (idx & 3) * 8;                                \
            unsigned off = (unsigned)((st) * TILEH + rr * LDT + cc) * 2u;         \
            CPA16((unsigned)__cvta_generic_to_shared(SA_h) + off,                 \
                  &g_Xh[(bm + rr) * NFEAT + (k0) + cc]);                          \
            CPA16((unsigned)__cvta_generic_to_shared(SA_l) + off,                 \
                  &g_Xl[(bm + rr) * NFEAT + (k0) + cc]);                          \
            CPA16((unsigned)__cvta_generic_to_shared(SB_h) + off,                 \
                  &g_Wh[(bn + rr) * NFEAT + (k0) + cc]);                          \
            CPA16((unsigned)__cvta_generic_to_shared(SB_l) + off,                 \
                  &g_Wl[(bn + rr) * NFEAT + (k0) + cc]);                          \
        }                                                                         \
        asm volatile("cp.async.commit_group;" ::: "memory");                      \
    } while (0)

    LOAD_STAGE(0, 0);

    for (int it = 0; it < NFEAT / 32; it++) {
        if (it + 1 < NFEAT / 32) {
            LOAD_STAGE((it + 1) & 1, (it + 1) * 32);
            asm volatile("cp.async.wait_group 1;" ::: "memory");
        } else {
            asm volatile("cp.async.wait_group 0;" ::: "memory");
        }
        __syncthreads();

        const uint32_t so = (uint32_t)((it & 1) * TILEH * 2);

#pragma unroll
        for (int kk = 0; kk < 32; kk += 16) {
            const uint32_t ko = so + (uint32_t)(kk * 2);
            uint32_t ah0[4], ah1[4], al0[4], al1[4];
            LDSM4(ah0, aAh + ko);
            LDSM4(ah1, aAh + 16 * LDT * 2 + ko);
            LDSM4(al0, aAl + ko);
            LDSM4(al1, aAl + 16 * LDT * 2 + ko);
#pragma unroll
            for (int p = 0; p < 4; p++) {
                uint32_t bh[4], bl[4];
                LDSM4(bh, aBh + (uint32_t)(p * 16 * LDT * 2) + ko);
                LDSM4(bl, aBl + (uint32_t)(p * 16 * LDT * 2) + ko);
                // nt = 2p: b0=bh[0], b1=bh[2]; nt = 2p+1: b0=bh[1], b1=bh[3]
                MMA16816(acc[0][2 * p],     ah0[0], ah0[1], ah0[2], ah0[3], bh[0], bh[2]);
                MMA16816(acc[1][2 * p],     ah1[0], ah1[1], ah1[2], ah1[3], bh[0], bh[2]);
                MMA16816(acc[0][2 * p + 1], ah0[0], ah0[1], ah0[2], ah0[3], bh[1], bh[3]);
                MMA16816(acc[1][2 * p + 1], ah1[0], ah1[1], ah1[2], ah1[3], bh[1], bh[3]);
                MMA16816(acc[0][2 * p],     al0[0], al0[1], al0[2], al0[3], bh[0], bh[2]);
                MMA16816(acc[1][2 * p],     al1[0], al1[1], al1[2], al1[3], bh[0], bh[2]);
                MMA16816(acc[0][2 * p + 1], al0[0], al0[1], al0[2], al0[3], bh[1], bh[3]);
                MMA16816(acc[1][2 * p + 1], al1[0], al1[1], al1[2], al1[3], bh[1], bh[3]);
                MMA16816(acc[0][2 * p],     ah0[0], ah0[1], ah0[2], ah0[3], bl[0], bl[2]);
                MMA16816(acc[1][2 * p],     ah1[0], ah1[1], ah1[2], ah1[3], bl[0], bl[2]);
                MMA16816(acc[0][2 * p + 1], ah0[0], ah0[1], ah0[2], ah0[3], bl[1], bl[3]);
                MMA16816(acc[1][2 * p + 1], ah1[0], ah1[1], ah1[2], ah1[3], bl[1], bl[3]);
            }
        }
        __syncthreads();
    }

    // epilogue: write fp32 H1 + fp16 copy
#pragma unroll
    for (int mt = 0; mt < 2; mt++) {
#pragma unroll
        for (int nt = 0; nt < 8; nt++) {
            int m = bm + wm * 32 + mt * 16 + g;
            int n = bn + wn * 64 + nt * 8 + tg * 2;
            float c0 = acc[mt][nt][0], c1 = acc[mt][nt][1];
            float c2 = acc[mt][nt][2], c3 = acc[mt][nt][3];
            *(float2*)&g_H1[m * HTOT + n]       = make_float2(c0, c1);
            *(float2*)&g_H1[(m + 8) * HTOT + n] = make_float2(c2, c3);
            *(__half2*)&g_H1h[m * HTOT + n]       = __floats2half2_rn(c0, c1);
            *(__half2*)&g_H1h[(m + 8) * HTOT + n] = __floats2half2_rn(c2, c3);
        }
    }

    // fused score1: this block owns complete head `head = 2*bx + wn` columns
    // for its 128 rows. Per-thread partials over nt, quad-reduce over tg.
    {
        const int head = 2 * blockIdx.x + wn;
        const float* ap = &a_heads[head * 2 * NHID];
#pragma unroll
        for (int mt = 0; mt < 2; mt++) {
            float ss0 = 0.f, st0 = 0.f, ss1 = 0.f, st1 = 0.f;
#pragma unroll
            for (int nt = 0; nt < 8; nt++) {
                int f = nt * 8 + tg * 2;        // 0..63 within head
                float a0 = ap[f],        a1 = ap[f + 1];
                float b0 = ap[64 + f],   b1 = ap[64 + f + 1];
                ss0 += acc[mt][nt][0] * a0 + acc[mt][nt][1] * a1;
                st0 += acc[mt][nt][0] * b0 + acc[mt][nt][1] * b1;
                ss1 += acc[mt][nt][2] * a0 + acc[mt][nt][3] * a1;
                st1 += acc[mt][nt][2] * b0 + acc[mt][nt][3] * b1;
            }
#pragma unroll
            for (int off = 1; off <= 2; off <<= 1) {
                ss0 += __shfl_xor_sync(0xffffffffu, ss0, off);
                st0 += __shfl_xor_sync(0xffffffffu, st0, off);
                ss1 += __shfl_xor_sync(0xffffffffu, ss1, off);
                st1 += __shfl_xor_sync(0xffffffffu, st1, off);
            }
            if (tg == 0) {
                int m0 = bm + wm * 32 + mt * 16 + g;
                g_s1s[m0 * NHEAD + head]       = ss0;
                g_s1t[m0 * NHEAD + head]       = st0;
                g_s1s[(m0 + 8) * NHEAD + head] = ss1;
                g_s1t[(m0 + 8) * NHEAD + head] = st1;
            }
        }
    }
}

// ---------------- layer-1 masked-softmax aggregation (fp16 gather) ----------
// One block (128 threads) per source row. Weights + per-head Z precomputed in
// shared memory; the hot gather loop is LDS(w) + LDG(uint2) + FMA only.
__global__ void __launch_bounds__(128) k_agg1(const float* __restrict__ b_heads) {
    __shared__ __align__(16) unsigned short lst[N_NODES];
    __shared__ float s_red[128];
    __shared__ float s_m[NHEAD];
    __shared__ float s_z[NHEAD];
    __shared__ int   s_tot[4];
    __shared__ float s_w[CAPW * NHEAD];   // 8 KB

    const int i    = blockIdx.x;
    const int tid  = threadIdx.x;
    const int lane = tid & 31;
    const int wid  = tid >> 5;

    // neighbor list via per-warp scans
    uint32_t word = g_adj[i * ADJ_W + tid];
    int c  = __popc(word);
    int sc = c;
#pragma unroll
    for (int off = 1; off < 32; off <<= 1) {
        int v = __shfl_up_sync(0xffffffffu, sc, off);
        if (lane >= off) sc += v;
    }
    if (lane == 31) s_tot[wid] = sc;
    __syncthreads();
    int base = sc - c;
#pragma unroll
    for (int w = 0; w < 4; w++)
        if (w < wid) base += s_tot[w];
    const int cnt = s_tot[0] + s_tot[1] + s_tot[2] + s_tot[3];
    {
        int hi = tid << 5;
        while (word) {
            int b = __ffs(word) - 1;
            word &= word - 1;
            lst[base++] = (unsigned short)(hi + b);
        }
    }
    __syncthreads();

    const bool pre    = (cnt <= CAPW);
    const int  hh8    = tid & 7;
    const int  nstart = tid >> 3;          // 0..15, stride 16

    // per-head max of t_j over neighbors; cache t_j in s_w on the fast path
    float mt = -1e30f;
    if (pre) {
        for (int n = nstart; n < cnt; n += 16) {
            float t = g_s1t[(int)lst[n] * NHEAD + hh8];
            s_w[n * NHEAD + hh8] = t;
            mt = fmaxf(mt, t);
        }
    } else {
        for (int n = nstart; n < cnt; n += 16)
            mt = fmaxf(mt, g_s1t[(int)lst[n] * NHEAD + hh8]);
    }
    s_red[tid] = mt;
    __syncthreads();
    if (tid < NHEAD) {
        float m = s_red[tid];
#pragma unroll
        for (int k = 1; k < 16; k++) m = fmaxf(m, s_red[tid + 8 * k]);
        float e = g_s1s[i * NHEAD + tid] + m;
        s_m[tid] = (e > 0.f) ? e : ALPHA_S * e;  // row max of lrelu scores
    }
    __syncthreads();

    // weight pass: s_w <- exp(lrelu(ss+t) - m), Z reduced per head
    float zacc = 0.f;
    if (pre) {
        float m  = s_m[hh8];
        float ss = g_s1s[i * NHEAD + hh8];
        for (int n = nstart; n < cnt; n += 16) {
            float e = ss + s_w[n * NHEAD + hh8];
            e = (e > 0.f) ? e : ALPHA_S * e;
            float w = __expf(e - m);
            s_w[n * NHEAD + hh8] = w;
            zacc += w;
        }
    }
    s_red[tid] = zacc;
    __syncthreads();
    if (tid < NHEAD) {
        float z = 0.f;
#pragma unroll
        for (int k = 0; k < 16; k++) z += s_red[tid + 8 * k];
        s_z[tid] = z;
    }
    __syncthreads();

    const int   c0 = tid * 4;          // owned columns c0..c0+3
    const int   hh = tid >> 4;         // head = c0/64
    float ax = 0.f, ay = 0.f, az = 0.f, aw = 0.f;
    float inv;

    if (cnt == 0) {
        // empty row: softmax over all-NEG_INF -> uniform 1/N over every node
        for (int j = 0; j < N_NODES; j++) {
            uint2 r0 = *(const uint2*)&g_H1h[j * HTOT + c0];
            float2 f0a = __half22float2(*(__half2*)&r0.x), f0b = __half22float2(*(__half2*)&r0.y);
            ax += f0a.x; ay += f0a.y; az += f0b.x; aw += f0b.y;
        }
        inv = 1.f / (float)N_NODES;
    } else if (pre) {
        int n = 0;
        for (; n + 4 <= cnt; n += 4) {
            uint2 jj = *(const uint2*)&lst[n];
            int j0 = jj.x & 0xffff, j1 = jj.x >> 16;
            int j2 = jj.y & 0xffff, j3 = jj.y >> 16;
            float w0 = s_w[(n + 0) * NHEAD + hh];
            float w1 = s_w[(n + 1) * NHEAD + hh];
            float w2 = s_w[(n + 2) * NHEAD + hh];
            float w3 = s_w[(n + 3) * NHEAD + hh];
            uint2 r0 = *(const uint2*)&g_H1h[j0 * HTOT + c0];
            uint2 r1 = *(const uint2*)&g_H1h[j1 * HTOT + c0];
            uint2 r2 = *(const uint2*)&g_H1h[j2 * HTOT + c0];
            uint2 r3 = *(const uint2*)&g_H1h[j3 * HTOT + c0];
            float2 f0a = __half22float2(*(__half2*)&r0.x), f0b = __half22float2(*(__half2*)&r0.y);
            float2 f1a = __half22float2(*(__half2*)&r1.x), f1b = __half22float2(*(__half2*)&r1.y);
            float2 f2a = __half22float2(*(__half2*)&r2.x), f2b = __half22float2(*(__half2*)&r2.y);
            float2 f3a = __half22float2(*(__half2*)&r3.x), f3b = __half22float2(*(__half2*)&r3.y);
            ax += w0 * f0a.x + w1 * f1a.x + w2 * f2a.x + w3 * f3a.x;
            ay += w0 * f0a.y + w1 * f1a.y + w2 * f2a.y + w3 * f3a.y;
            az += w0 * f0b.x + w1 * f1b.x + w2 * f2b.x + w3 * f3b.x;
            aw += w0 * f0b.y + w1 * f1b.y + w2 * f2b.y + w3 * f3b.y;
        }
        for (; n < cnt; n++) {
            int j = lst[n];
            float w0 = s_w[n * NHEAD + hh];
            uint2 r0 = *(const uint2*)&g_H1h[j * HTOT + c0];
            float2 f0a = __half22float2(*(__half2*)&r0.x), f0b = __half22float2(*(__half2*)&r0.y);
            ax += w0 * f0a.x; ay += w0 * f0a.y; az += w0 * f0b.x; aw += w0 * f0b.y;
        }
        inv = 1.f / s_z[hh];
    } else {
        // fallback (cnt > CAPW): inline weights
        const float m  = s_m[hh];
        const float ss = g_s1s[i * NHEAD + hh];
        float Z = 0.f;
        for (int n = 0; n < cnt; n++) {
            int j = lst[n];
            float e = ss + g_s1t[j * NHEAD + hh];
            e = (e > 0.f) ? e : ALPHA_S * e;
            float w0 = __expf(e - m);
            Z += w0;
            uint2 r0 = *(const uint2*)&g_H1h[j * HTOT + c0];
            float2 f0a = __half22float2(*(__half2*)&r0.x), f0b = __half22float2(*(__half2*)&r0.y);
            ax += w0 * f0a.x; ay += w0 * f0a.y; az += w0 * f0b.x; aw += w0 * f0b.y;
        }
        inv = 1.f / Z;
    }

    float4 b4 = *(const float4*)&b_heads[hh * NHID + (c0 & 63)];
    float vx = ax * inv + b4.x; vx = (vx > 0.f) ? vx : expm1f(vx);
    float vy = ay * inv + b4.y; vy = (vy > 0.f) ? vy : expm1f(vy);
    float vz = az * inv + b4.z; vz = (vz > 0.f) ? vz : expm1f(vz);
    float vw = aw * inv + b4.w; vw = (vw > 0.f) ? vw : expm1f(vw);
    *(float4*)&g_X2[i * HTOT + c0] = make_float4(vx, vy, vz, vw);
}

// ---------------- GEMM2: H2 = X2 @ W_out, fused score2 ----------------------
__global__ void __launch_bounds__(256) k_gemm2(const float* __restrict__ Wout,
                                               const float* __restrict__ a_out) {
    __shared__ float Ws[NFEAT * NCLASS];  // 32 KB
    int tid = threadIdx.x;
    for (int idx = tid; idx < NFEAT * NCLASS; idx += 256) Ws[idx] = Wout[idx];
    __syncthreads();
    int row = blockIdx.x * 16 + (tid >> 4);
    int col = tid & 15;
    const float* x = &g_X2[row * HTOT];
    float acc = 0.f;
#pragma unroll 4
    for (int k = 0; k < NFEAT; k += 4) {
        float4 xv = *(const float4*)&x[k];
        acc += xv.x * Ws[(k + 0) * NCLASS + col];
        acc += xv.y * Ws[(k + 1) * NCLASS + col];
        acc += xv.z * Ws[(k + 2) * NCLASS + col];
        acc += xv.w * Ws[(k + 3) * NCLASS + col];
    }
    g_H2[row * NCLASS + col] = acc;

    // fused score2: reduce over the 16 lanes holding this row
    float vs = acc * a_out[col];
    float vt = acc * a_out[NCLASS + col];
#pragma unroll
    for (int off = 8; off; off >>= 1) {
        vs += __shfl_xor_sync(0xffffffffu, vs, off);
        vt += __shfl_xor_sync(0xffffffffu, vt, off);
    }
    if ((tid & 15) == 0) {
        g_s2s[row] = vs;
        g_s2t[row] = vt;
    }
}

// ---------------- layer-2 aggregation + log_softmax -------------------------
// One warp per source row, 4 rows per block.
__global__ void __launch_bounds__(128) k_agg2(const float* __restrict__ b_out,
                                              float* __restrict__ out) {
    __shared__ unsigned short lst[4][N_NODES];
    const int wid  = threadIdx.x >> 5;
    const int lane = threadIdx.x & 31;
    const int i    = blockIdx.x * 4 + wid;

    // deterministic per-warp neighbor list (4 rounds of 32 words, warp scans)
    int base_acc = 0;
#pragma unroll
    for (int r = 0; r < 4; r++) {
        uint32_t word = g_adj[i * ADJ_W + r * 32 + lane];
        int c = __popc(word);
        int sc = c;
#pragma unroll
        for (int off = 1; off < 32; off <<= 1) {
            int v = __shfl_up_sync(0xffffffffu, sc, off);
            if (lane >= off) sc += v;
        }
        int base  = base_acc + sc - c;
        int total = __shfl_sync(0xffffffffu, sc, 31);
        int hi = (r * 32 + lane) << 5;
        while (word) {
            int b = __ffs(word) - 1;
            word &= word - 1;
            lst[wid][base++] = (unsigned short)(hi + b);
        }
        base_acc += total;
    }
    __syncwarp();
    const int cnt = base_acc;
    const float ssrc = g_s2s[i];

    float mt = -1e30f;
    for (int n = lane; n < cnt; n += 32) mt = fmaxf(mt, g_s2t[(int)lst[wid][n]]);
#pragma unroll
    for (int off = 16; off; off >>= 1)
        mt = fmaxf(mt, __shfl_xor_sync(0xffffffffu, mt, off));
    float m = ssrc + mt;
    m = (m > 0.f) ? m : ALPHA_S * m;

    float acc[NCLASS];
#pragma unroll
    for (int k = 0; k < NCLASS; k++) acc[k] = 0.f;
    float Z = 0.f;

    if (cnt > 0) {
        for (int n = lane; n < cnt; n += 32) {
            int j = lst[wid][n];
            float e = ssrc + g_s2t[j];
            e = (e > 0.f) ? e : ALPHA_S * e;
            float w = __expf(e - m);
            Z += w;
            const float4* hp = (const float4*)&g_H2[j * NCLASS];
            float4 v0 = hp[0], v1 = hp[1], v2 = hp[2], v3 = hp[3];
            acc[0]  += w * v0.x; acc[1]  += w * v0.y; acc[2]  += w * v0.z; acc[3]  += w * v0.w;
            acc[4]  += w * v1.x; acc[5]  += w * v1.y; acc[6]  += w * v1.z; acc[7]  += w * v1.w;
            acc[8]  += w * v2.x; acc[9]  += w * v2.y; acc[10] += w * v2.z; acc[11] += w * v2.w;
            acc[12] += w * v3.x; acc[13] += w * v3.y; acc[14] += w * v3.z; acc[15] += w * v3.w;
        }
    } else {
        for (int j = lane; j < N_NODES; j += 32) {
            Z += 1.f;
            const float4* hp = (const float4*)&g_H2[j * NCLASS];
            float4 v0 = hp[0], v1 = hp[1], v2 = hp[2], v3 = hp[3];
            acc[0]  += v0.x; acc[1]  += v0.y; acc[2]  += v0.z; acc[3]  += v0.w;
            acc[4]  += v1.x; acc[5]  += v1.y; acc[6]  += v1.z; acc[7]  += v1.w;
            acc[8]  += v2.x; acc[9]  += v2.y; acc[10] += v2.z; acc[11] += v2.w;
            acc[12] += v3.x; acc[13] += v3.y; acc[14] += v3.z; acc[15] += v3.w;
        }
    }

#pragma unroll
    for (int off = 16; off; off >>= 1) {
        Z += __shfl_xor_sync(0xffffffffu, Z, off);
#pragma unroll
        for (int k = 0; k < NCLASS; k++)
            acc[k] += __shfl_xor_sync(0xffffffffu, acc[k], off);
    }

    if (lane == 0) {
        float invZ = 1.f / Z;
        float v[NCLASS];
        float mx = -1e30f;
#pragma unroll
        for (int k = 0; k < NCLASS; k++) {
            v[k] = acc[k] * invZ + b_out[k];
            mx = fmaxf(mx, v[k]);
        }
        float s = 0.f;
#pragma unroll
        for (int k = 0; k < NCLASS; k++) s += __expf(v[k] - mx);
        float ls = mx + logf(s);
#pragma unroll
        for (int k = 0; k < NCLASS; k++) out[i * NCLASS + k] = v[k] - ls;
    }
}

// ---------------- launch ------------------------------------------------------
extern "C" void kernel_launch(void* const* d_in, const int* in_sizes, int n_in,
                              void* d_out, int out_size) {
    const float* features = (const float*)d_in[0];
    const void*  edges    = d_in[1];
    const float* W_heads  = (const float*)d_in[2];
    const float* a_heads  = (const float*)d_in[3];
    const float* b_heads  = (const float*)d_in[4];
    const float* W_out    = (const float*)d_in[5];
    const float* a_out    = (const float*)d_in[6];
    const float* b_out    = (const float*)d_in[7];
    float* out = (float*)d_out;

    const int smem_g1 = 8 * TILEH * (int)sizeof(__half);   // 80 KB
    cudaFuncSetAttribute(k_gemm1_tc, cudaFuncAttributeMaxDynamicSharedMemorySize, smem_g1);

    void* adj_ptr = nullptr;
    cudaGetSymbolAddress(&adj_ptr, g_adj);
    cudaMemsetAsync(adj_ptr, 0, N_NODES * ADJ_W * sizeof(uint32_t), 0);

    k_detect<<<1, 1>>>((const uint32_t*)edges);
    k_scatter<<<N_EDGES / 256, 256>>>(edges);
    k_prep<<<1280, 1024>>>(features, W_heads);
    {
        dim3 g(HTOT / 128, N_NODES / 128);
        k_gemm1_tc<<<g, 256, smem_g1>>>(a_heads);
    }
    k_agg1<<<N_NODES, 128>>>(b_heads);
    k_gemm2<<<N_NODES / 16, 256>>>(W_out, a_out);
    k_agg2<<<N_NODES / 4, 128>>>(b_out, out);
}

// round 16
// speedup vs baseline: 1.0821x; 1.0821x over previous
#include <cuda_runtime.h>
#include <cuda_fp16.h>
#include <cstdint>

#define N_NODES 4096
#define N_EDGES 262144
#define NFEAT   512
#define NHID    64
#define NHEAD   8
#define HTOT    512   // NHEAD*NHID
#define NCLASS  16
#define ALPHA_S 0.2f
#define ADJ_W   128   // words per bitmap row (4096/32)
#define CAPW    256   // max neighbors for precomputed-weight fast path

// ---------------- scratch (static device globals; no allocation) ------------
__device__ uint32_t g_adj[N_NODES * ADJ_W];     // 2 MB adjacency bitmap (src rows)
__device__ __half   g_Xh [N_NODES * NFEAT];     // features split hi (fp16)
__device__ __half   g_Xl [N_NODES * NFEAT];     // features split lo (fp16)
__device__ __half   g_Wh [HTOT * NFEAT];        // W1 packed+transposed [n][k], hi
__device__ __half   g_Wl [HTOT * NFEAT];        // W1 packed+transposed [n][k], lo
__device__ float    g_H1 [N_NODES * HTOT];      // layer-1 per-head features (fp32)
__device__ __half   g_H1h[N_NODES * HTOT];      // fp16 copy for the gather
__device__ float    g_X2 [N_NODES * HTOT];      // elu(agg1) = layer-2 input
__device__ float    g_H2 [N_NODES * NCLASS];    // layer-2 projected features
__device__ float    g_s1s[N_NODES * NHEAD];     // layer-1 src scores
__device__ float    g_s1t[N_NODES * NHEAD];     // layer-1 tgt scores
__device__ float    g_s2s[N_NODES];
__device__ float    g_s2t[N_NODES];
__device__ int      g_is64;

// Detect int64 vs int32 edge buffer: int64 little-endian values <4096 have all
// odd 32-bit words == 0; int32 odd words are random node ids (P(all 0) ~ 0).
__global__ void k_detect(const uint32_t* __restrict__ el) {
    uint32_t acc = 0;
#pragma unroll
    for (int i = 1; i < 256; i += 2) acc |= el[i];
    g_is64 = (acc == 0u) ? 1 : 0;
}

__global__ void k_scatter(const void* __restrict__ elv) {
    int e = blockIdx.x * blockDim.x + threadIdx.x;
    if (e >= N_EDGES) return;
    int src, tgt;
    if (g_is64) {
        const long long* el = (const long long*)elv;
        src = (int)el[e]; tgt = (int)el[N_EDGES + e];
    } else {
        const int* el = (const int*)elv;
        src = el[e]; tgt = el[N_EDGES + e];
    }
    src &= (N_NODES - 1); tgt &= (N_NODES - 1);
    atomicOr(&g_adj[src * ADJ_W + (tgt >> 5)], 1u << (tgt & 31));
}

// ---------------- prep: coalesced W pack/transpose + X hi/lo split ----------
// blocks [0,256): W_heads [8,512,64] -> g_W{h,l}[n=512][k=512] via 32x32 tiles
// blocks [256,1280): split features (2M elems, 2 per thread)
__global__ void __launch_bounds__(1024) k_prep(const float* __restrict__ X,
                                               const float* __restrict__ W) {
    int b = blockIdx.x;
    if (b < 256) {
        __shared__ float t[32][33];
        int h  = b >> 5;
        int kt = (b >> 1) & 15;
        int ft = b & 1;
        int tx = threadIdx.x & 31, ty = threadIdx.x >> 5;
        t[ty][tx] = W[h * (NFEAT * NHID) + (kt * 32 + ty) * NHID + ft * 32 + tx];
        __syncthreads();
        float w = t[tx][ty];
        __half hi = __float2half_rn(w);
        __half lo = __float2half_rn(w - __half2float(hi));
        int o = (h * 64 + ft * 32 + ty) * NFEAT + kt * 32 + tx;
        g_Wh[o] = hi;
        g_Wl[o] = lo;
    } else {
        int i = (b - 256) * 2048 + threadIdx.x;
#pragma unroll
        for (int u = 0; u < 2; u++, i += 1024) {
            float x = X[i];
            __half hi = __float2half_rn(x);
            g_Xh[i] = hi;
            g_Xl[i] = __float2half_rn(x - __half2float(hi));
        }
    }
}

// ---------------- GEMM1 on tensor cores (split-fp16, fp32-exact) ------------
// C = Ah@Bh + Ah@Bl + Al@Bh.  BM=128, BN=128, BK=32, 2-stage cp.async pipeline,
// ldmatrix.x4 fragment loads. 16 warps (4m x 4n), warp tile 32x32, m16n8k16.
// Epilogue also computes the per-(row,head) score halves (fused k_score1).
#define LDT   40       // smem row stride in halves (32 + 8 pad)
#define TILEH (128 * LDT)

#define MMA16816(d, a0, a1, a2, a3, b0, b1)                                   \
    asm volatile(                                                             \
        "mma.sync.aligned.m16n8k16.row.col.f32.f16.f16.f32 "                  \
        "{%0,%1,%2,%3}, {%4,%5,%6,%7}, {%8,%9}, {%0,%1,%2,%3};"               \
        : "+f"(d[0]), "+f"(d[1]), "+f"(d[2]), "+f"(d[3])                      \
        : "r"(a0), "r"(a1), "r"(a2), "r"(a3), "r"(b0), "r"(b1))

#define LDSM4(r, addr)                                                        \
    asm volatile("ldmatrix.sync.aligned.m8n8.x4.shared.b16 {%0,%1,%2,%3}, [%4];" \
                 : "=r"((r)[0]), "=r"((r)[1]), "=r"((r)[2]), "=r"((r)[3])     \
                 : "r"(addr))

#define CPA16(smemaddr, gptr)                                                 \
    asm volatile("cp.async.ca.shared.global [%0], [%1], 16;"                  \
                 :: "r"(smemaddr), "l"(gptr) : "memory")

__global__ void __launch_bounds__(512) k_gemm1_tc(const float* __restrict__ a_heads) {
    extern __shared__ __half sm[];
    __half* SA_h = sm;                 // [2][TILEH]
    __half* SA_l = sm + 2 * TILEH;
    __half* SB_h = sm + 4 * TILEH;
    __half* SB_l = sm + 6 * TILEH;

    const int tid  = threadIdx.x;
    const int lane = tid & 31;
    const int warp = tid >> 5;
    const int wm   = warp >> 2;           // 0..3
    const int wn   = warp & 3;            // 0..3
    const int bm   = blockIdx.y * 128;
    const int bn   = blockIdx.x * 128;
    const int g    = lane >> 2;           // 0..7
    const int tg   = lane & 3;            // 0..3

    float acc[2][4][4];
#pragma unroll
    for (int i = 0; i < 2; i++)
#pragma unroll
        for (int j = 0; j < 4; j++)
#pragma unroll
            for (int k = 0; k < 4; k++) acc[i][j][k] = 0.f;

    // per-lane ldmatrix base addresses (bytes): row = base + (lane&15),
    // col = (lane>>4)*8 halves
    const int lrow = lane & 15;
    const int lcol = (lane >> 4) * 8;
    const uint32_t aAh = (uint32_t)__cvta_generic_to_shared(SA_h) +
                         (uint32_t)(((wm * 32 + lrow) * LDT + lcol) * 2);
    const uint32_t aAl = (uint32_t)__cvta_generic_to_shared(SA_l) +
                         (uint32_t)(((wm * 32 + lrow) * LDT + lcol) * 2);
    const uint32_t aBh = (uint32_t)__cvta_generic_to_shared(SB_h) +
                         (uint32_t)(((wn * 32 + lrow) * LDT + lcol) * 2);
    const uint32_t aBl = (uint32_t)__cvta_generic_to_shared(SB_l) +
                         (uint32_t)(((wn * 32 + lrow) * LDT + lcol) * 2);

#define LOAD_STAGE(st, k0)                                                        \
    do {                                                                          \
        int rr = tid >> 2, cc = (tid & 3) * 8;                                    \
        unsigned off = (unsigned)((st) * TILEH + rr * LDT + cc) * 2u;             \
        CPA16((unsigned)__cvta_generic_to_shared(SA_h) + off,                     \
              &g_Xh[(bm + rr) * NFEAT + (k0) + cc]);                              \
        CPA16((unsigned)__cvta_generic_to_shared(SA_l) + off,                     \
              &g_Xl[(bm + rr) * NFEAT + (k0) + cc]);                              \
        CPA16((unsigned)__cvta_generic_to_shared(SB_h) + off,                     \
              &g_Wh[(bn + rr) * NFEAT + (k0) + cc]);                              \
        CPA16((unsigned)__cvta_generic_to_shared(SB_l) + off,                     \
              &g_Wl[(bn + rr) * NFEAT + (k0) + cc]);                              \
        asm volatile("cp.async.commit_group;" ::: "memory");                      \
    } while (0)

    LOAD_STAGE(0, 0);

    for (int it = 0; it < NFEAT / 32; it++) {
        if (it + 1 < NFEAT / 32) {
            LOAD_STAGE((it + 1) & 1, (it + 1) * 32);
            asm volatile("cp.async.wait_group 1;" ::: "memory");
        } else {
            asm volatile("cp.async.wait_group 0;" ::: "memory");
        }
        __syncthreads();

        const uint32_t so = (uint32_t)((it & 1) * TILEH * 2);

#pragma unroll
        for (int kk = 0; kk < 32; kk += 16) {
            const uint32_t ko = so + (uint32_t)(kk * 2);
            uint32_t ah0[4], ah1[4], al0[4], al1[4];
            LDSM4(ah0, aAh + ko);
            LDSM4(ah1, aAh + 16 * LDT * 2 + ko);
            LDSM4(al0, aAl + ko);
            LDSM4(al1, aAl + 16 * LDT * 2 + ko);
            uint32_t bh0[4], bh1[4], bl0[4], bl1[4];
            LDSM4(bh0, aBh + ko);                 // nt 0,1
            LDSM4(bh1, aBh + 16 * LDT * 2 + ko);  // nt 2,3
            LDSM4(bl0, aBl + ko);
            LDSM4(bl1, aBl + 16 * LDT * 2 + ko);

            MMA16816(acc[0][0], ah0[0], ah0[1], ah0[2], ah0[3], bh0[0], bh0[2]);
            MMA16816(acc[1][0], ah1[0], ah1[1], ah1[2], ah1[3], bh0[0], bh0[2]);
            MMA16816(acc[0][1], ah0[0], ah0[1], ah0[2], ah0[3], bh0[1], bh0[3]);
            MMA16816(acc[1][1], ah1[0], ah1[1], ah1[2], ah1[3], bh0[1], bh0[3]);
            MMA16816(acc[0][2], ah0[0], ah0[1], ah0[2], ah0[3], bh1[0], bh1[2]);
            MMA16816(acc[1][2], ah1[0], ah1[1], ah1[2], ah1[3], bh1[0], bh1[2]);
            MMA16816(acc[0][3], ah0[0], ah0[1], ah0[2], ah0[3], bh1[1], bh1[3]);
            MMA16816(acc[1][3], ah1[0], ah1[1], ah1[2], ah1[3], bh1[1], bh1[3]);

            MMA16816(acc[0][0], al0[0], al0[1], al0[2], al0[3], bh0[0], bh0[2]);
            MMA16816(acc[1][0], al1[0], al1[1], al1[2], al1[3], bh0[0], bh0[2]);
            MMA16816(acc[0][1], al0[0], al0[1], al0[2], al0[3], bh0[1], bh0[3]);
            MMA16816(acc[1][1], al1[0], al1[1], al1[2], al1[3], bh0[1], bh0[3]);
            MMA16816(acc[0][2], al0[0], al0[1], al0[2], al0[3], bh1[0], bh1[2]);
            MMA16816(acc[1][2], al1[0], al1[1], al1[2], al1[3], bh1[0], bh1[2]);
            MMA16816(acc[0][3], al0[0], al0[1], al0[2], al0[3], bh1[1], bh1[3]);
            MMA16816(acc[1][3], al1[0], al1[1], al1[2], al1[3], bh1[1], bh1[3]);

            MMA16816(acc[0][0], ah0[0], ah0[1], ah0[2], ah0[3], bl0[0], bl0[2]);
            MMA16816(acc[1][0], ah1[0], ah1[1], ah1[2], ah1[3], bl0[0], bl0[2]);
            MMA16816(acc[0][1], ah0[0], ah0[1], ah0[2], ah0[3], bl0[1], bl0[3]);
            MMA16816(acc[1][1], ah1[0], ah1[1], ah1[2], ah1[3], bl0[1], bl0[3]);
            MMA16816(acc[0][2], ah0[0], ah0[1], ah0[2], ah0[3], bl1[0], bl1[2]);
            MMA16816(acc[1][2], ah1[0], ah1[1], ah1[2], ah1[3], bl1[0], bl1[2]);
            MMA16816(acc[0][3], ah0[0], ah0[1], ah0[2], ah0[3], bl1[1], bl1[3]);
            MMA16816(acc[1][3], ah1[0], ah1[1], ah1[2], ah1[3], bl1[1], bl1[3]);
        }
        __syncthreads();
    }

    // epilogue: write fp32 H1 + fp16 copy
#pragma unroll
    for (int mt = 0; mt < 2; mt++) {
#pragma unroll
        for (int nt = 0; nt < 4; nt++) {
            int m = bm + wm * 32 + mt * 16 + g;
            int n = bn + wn * 32 + nt * 8 + tg * 2;
            float c0 = acc[mt][nt][0], c1 = acc[mt][nt][1];
            float c2 = acc[mt][nt][2], c3 = acc[mt][nt][3];
            *(float2*)&g_H1[m * HTOT + n]       = make_float2(c0, c1);
            *(float2*)&g_H1[(m + 8) * HTOT + n] = make_float2(c2, c3);
            *(__half2*)&g_H1h[m * HTOT + n]       = __floats2half2_rn(c0, c1);
            *(__half2*)&g_H1h[(m + 8) * HTOT + n] = __floats2half2_rn(c2, c3);
        }
    }

    // fused score1: head = 2*bx + (wn>>1); warps wn and wn^1 each own half the
    // head's 64 columns. Per-warp quad-reduced partials -> smem -> pair-add.
    {
        float* sp = (float*)sm;   // tiles are dead after the last barrier
        const int head = 2 * blockIdx.x + (wn >> 1);
        const float* ap = &a_heads[head * 2 * NHID];
#pragma unroll
        for (int mt = 0; mt < 2; mt++) {
            float ss0 = 0.f, st0 = 0.f, ss1 = 0.f, st1 = 0.f;
#pragma unroll
            for (int nt = 0; nt < 4; nt++) {
                int f = (wn & 1) * 32 + nt * 8 + tg * 2;   // 0..63 within head
                float a0 = ap[f],        a1 = ap[f + 1];
                float b0 = ap[64 + f],   b1 = ap[64 + f + 1];
                ss0 += acc[mt][nt][0] * a0 + acc[mt][nt][1] * a1;
                st0 += acc[mt][nt][0] * b0 + acc[mt][nt][1] * b1;
                ss1 += acc[mt][nt][2] * a0 + acc[mt][nt][3] * a1;
                st1 += acc[mt][nt][2] * b0 + acc[mt][nt][3] * b1;
            }
#pragma unroll
            for (int off = 1; off <= 2; off <<= 1) {
                ss0 += __shfl_xor_sync(0xffffffffu, ss0, off);
                st0 += __shfl_xor_sync(0xffffffffu, st0, off);
                ss1 += __shfl_xor_sync(0xffffffffu, ss1, off);
                st1 += __shfl_xor_sync(0xffffffffu, st1, off);
            }
            if (tg == 0) {
                int b = (warp * 2 + mt) * 32 + g * 4;
                sp[b + 0] = ss0; sp[b + 1] = st0;
                sp[b + 2] = ss1; sp[b + 3] = st1;
            }
        }
        __syncthreads();
        if ((wn & 1) == 0 && tg == 0) {
#pragma unroll
            for (int mt = 0; mt < 2; mt++) {
                int b0 = (warp * 2 + mt) * 32 + g * 4;
                int b1 = ((warp + 1) * 2 + mt) * 32 + g * 4;
                float ss0 = sp[b0 + 0] + sp[b1 + 0];
                float st0 = sp[b0 + 1] + sp[b1 + 1];
                float ss1 = sp[b0 + 2] + sp[b1 + 2];
                float st1 = sp[b0 + 3] + sp[b1 + 3];
                int m0 = bm + wm * 32 + mt * 16 + g;
                g_s1s[m0 * NHEAD + head]       = ss0;
                g_s1t[m0 * NHEAD + head]       = st0;
                g_s1s[(m0 + 8) * NHEAD + head] = ss1;
                g_s1t[(m0 + 8) * NHEAD + head] = st1;
            }
        }
    }
}

// ---------------- layer-1 masked-softmax aggregation (fp16 gather) ----------
// One block (128 threads) per source row. Weights + per-head Z precomputed in
// shared memory; the hot gather loop is LDS(w) + LDG(uint2) + FMA only.
__global__ void __launch_bounds__(128) k_agg1(const float* __restrict__ b_heads) {
    __shared__ __align__(16) unsigned short lst[N_NODES];
    __shared__ float s_red[128];
    __shared__ float s_m[NHEAD];
    __shared__ float s_z[NHEAD];
    __shared__ int   s_tot[4];
    __shared__ float s_w[CAPW * NHEAD];   // 8 KB

    const int i    = blockIdx.x;
    const int tid  = threadIdx.x;
    const int lane = tid & 31;
    const int wid  = tid >> 5;

    // neighbor list via per-warp scans
    uint32_t word = g_adj[i * ADJ_W + tid];
    int c  = __popc(word);
    int sc = c;
#pragma unroll
    for (int off = 1; off < 32; off <<= 1) {
        int v = __shfl_up_sync(0xffffffffu, sc, off);
        if (lane >= off) sc += v;
    }
    if (lane == 31) s_tot[wid] = sc;
    __syncthreads();
    int base = sc - c;
#pragma unroll
    for (int w = 0; w < 4; w++)
        if (w < wid) base += s_tot[w];
    const int cnt = s_tot[0] + s_tot[1] + s_tot[2] + s_tot[3];
    {
        int hi = tid << 5;
        while (word) {
            int b = __ffs(word) - 1;
            word &= word - 1;
            lst[base++] = (unsigned short)(hi + b);
        }
    }
    __syncthreads();

    const bool pre    = (cnt <= CAPW);
    const int  hh8    = tid & 7;
    const int  nstart = tid >> 3;          // 0..15, stride 16

    // per-head max of t_j over neighbors; cache t_j in s_w on the fast path
    float mt = -1e30f;
    if (pre) {
        for (int n = nstart; n < cnt; n += 16) {
            float t = g_s1t[(int)lst[n] * NHEAD + hh8];
            s_w[n * NHEAD + hh8] = t;
            mt = fmaxf(mt, t);
        }
    } else {
        for (int n = nstart; n < cnt; n += 16)
            mt = fmaxf(mt, g_s1t[(int)lst[n] * NHEAD + hh8]);
    }
    s_red[tid] = mt;
    __syncthreads();
    if (tid < NHEAD) {
        float m = s_red[tid];
#pragma unroll
        for (int k = 1; k < 16; k++) m = fmaxf(m, s_red[tid + 8 * k]);
        float e = g_s1s[i * NHEAD + tid] + m;
        s_m[tid] = (e > 0.f) ? e : ALPHA_S * e;  // row max of lrelu scores
    }
    __syncthreads();

    // weight pass: s_w <- exp(lrelu(ss+t) - m), Z reduced per head
    float zacc = 0.f;
    if (pre) {
        float m  = s_m[hh8];
        float ss = g_s1s[i * NHEAD + hh8];
        for (int n = nstart; n < cnt; n += 16) {
            float e = ss + s_w[n * NHEAD + hh8];
            e = (e > 0.f) ? e : ALPHA_S * e;
            float w = __expf(e - m);
            s_w[n * NHEAD + hh8] = w;
            zacc += w;
        }
    }
    s_red[tid] = zacc;
    __syncthreads();
    if (tid < NHEAD) {
        float z = 0.f;
#pragma unroll
        for (int k = 0; k < 16; k++) z += s_red[tid + 8 * k];
        s_z[tid] = z;
    }
    __syncthreads();

    const int   c0 = tid * 4;          // owned columns c0..c0+3
    const int   hh = tid >> 4;         // head = c0/64
    float ax = 0.f, ay = 0.f, az = 0.f, aw = 0.f;
    float inv;

    if (cnt == 0) {
        // empty row: softmax over all-NEG_INF -> uniform 1/N over every node
        for (int j = 0; j < N_NODES; j++) {
            uint2 r0 = *(const uint2*)&g_H1h[j * HTOT + c0];
            float2 f0a = __half22float2(*(__half2*)&r0.x), f0b = __half22float2(*(__half2*)&r0.y);
            ax += f0a.x; ay += f0a.y; az += f0b.x; aw += f0b.y;
        }
        inv = 1.f / (float)N_NODES;
    } else if (pre) {
        int n = 0;
        for (; n + 4 <= cnt; n += 4) {
            uint2 jj = *(const uint2*)&lst[n];
            int j0 = jj.x & 0xffff, j1 = jj.x >> 16;
            int j2 = jj.y & 0xffff, j3 = jj.y >> 16;
            float w0 = s_w[(n + 0) * NHEAD + hh];
            float w1 = s_w[(n + 1) * NHEAD + hh];
            float w2 = s_w[(n + 2) * NHEAD + hh];
            float w3 = s_w[(n + 3) * NHEAD + hh];
            uint2 r0 = *(const uint2*)&g_H1h[j0 * HTOT + c0];
            uint2 r1 = *(const uint2*)&g_H1h[j1 * HTOT + c0];
            uint2 r2 = *(const uint2*)&g_H1h[j2 * HTOT + c0];
            uint2 r3 = *(const uint2*)&g_H1h[j3 * HTOT + c0];
            float2 f0a = __half22float2(*(__half2*)&r0.x), f0b = __half22float2(*(__half2*)&r0.y);
            float2 f1a = __half22float2(*(__half2*)&r1.x), f1b = __half22float2(*(__half2*)&r1.y);
            float2 f2a = __half22float2(*(__half2*)&r2.x), f2b = __half22float2(*(__half2*)&r2.y);
            float2 f3a = __half22float2(*(__half2*)&r3.x), f3b = __half22float2(*(__half2*)&r3.y);
            ax += w0 * f0a.x + w1 * f1a.x + w2 * f2a.x + w3 * f3a.x;
            ay += w0 * f0a.y + w1 * f1a.y + w2 * f2a.y + w3 * f3a.y;
            az += w0 * f0b.x + w1 * f1b.x + w2 * f2b.x + w3 * f3b.x;
            aw += w0 * f0b.y + w1 * f1b.y + w2 * f2b.y + w3 * f3b.y;
        }
        for (; n < cnt; n++) {
            int j = lst[n];
            float w0 = s_w[n * NHEAD + hh];
            uint2 r0 = *(const uint2*)&g_H1h[j * HTOT + c0];
            float2 f0a = __half22float2(*(__half2*)&r0.x), f0b = __half22float2(*(__half2*)&r0.y);
            ax += w0 * f0a.x; ay += w0 * f0a.y; az += w0 * f0b.x; aw += w0 * f0b.y;
        }
        inv = 1.f / s_z[hh];
    } else {
        // fallback (cnt > CAPW): inline weights
        const float m  = s_m[hh];
        const float ss = g_s1s[i * NHEAD + hh];
        float Z = 0.f;
        for (int n = 0; n < cnt; n++) {
            int j = lst[n];
            float e = ss + g_s1t[j * NHEAD + hh];
            e = (e > 0.f) ? e : ALPHA_S * e;
            float w0 = __expf(e - m);
            Z += w0;
            uint2 r0 = *(const uint2*)&g_H1h[j * HTOT + c0];
            float2 f0a = __half22float2(*(__half2*)&r0.x), f0b = __half22float2(*(__half2*)&r0.y);
            ax += w0 * f0a.x; ay += w0 * f0a.y; az += w0 * f0b.x; aw += w0 * f0b.y;
        }
        inv = 1.f / Z;
    }

    float4 b4 = *(const float4*)&b_heads[hh * NHID + (c0 & 63)];
    float vx = ax * inv + b4.x; vx = (vx > 0.f) ? vx : expm1f(vx);
    float vy = ay * inv + b4.y; vy = (vy > 0.f) ? vy : expm1f(vy);
    float vz = az * inv + b4.z; vz = (vz > 0.f) ? vz : expm1f(vz);
    float vw = aw * inv + b4.w; vw = (vw > 0.f) ? vw : expm1f(vw);
    *(float4*)&g_X2[i * HTOT + c0] = make_float4(vx, vy, vz, vw);
}

// ---------------- GEMM2: H2 = X2 @ W_out, fused score2 ----------------------
__global__ void __launch_bounds__(256) k_gemm2(const float* __restrict__ Wout,
                                               const float* __restrict__ a_out) {
    __shared__ float Ws[NFEAT * NCLASS];  // 32 KB
    int tid = threadIdx.x;
    for (int idx = tid; idx < NFEAT * NCLASS; idx += 256) Ws[idx] = Wout[idx];
    __syncthreads();
    int row = blockIdx.x * 16 + (tid >> 4);
    int col = tid & 15;
    const float* x = &g_X2[row * HTOT];
    float acc = 0.f;
#pragma unroll 4
    for (int k = 0; k < NFEAT; k += 4) {
        float4 xv = *(const float4*)&x[k];
        acc += xv.x * Ws[(k + 0) * NCLASS + col];
        acc += xv.y * Ws[(k + 1) * NCLASS + col];
        acc += xv.z * Ws[(k + 2) * NCLASS + col];
        acc += xv.w * Ws[(k + 3) * NCLASS + col];
    }
    g_H2[row * NCLASS + col] = acc;

    // fused score2: reduce over the 16 lanes holding this row
    float vs = acc * a_out[col];
    float vt = acc * a_out[NCLASS + col];
#pragma unroll
    for (int off = 8; off; off >>= 1) {
        vs += __shfl_xor_sync(0xffffffffu, vs, off);
        vt += __shfl_xor_sync(0xffffffffu, vt, off);
    }
    if ((tid & 15) == 0) {
        g_s2s[row] = vs;
        g_s2t[row] = vt;
    }
}

// ---------------- layer-2 aggregation + log_softmax -------------------------
// One warp per source row, 4 rows per block.
__global__ void __launch_bounds__(128) k_agg2(const float* __restrict__ b_out,
                                              float* __restrict__ out) {
    __shared__ unsigned short lst[4][N_NODES];
    const int wid  = threadIdx.x >> 5;
    const int lane = threadIdx.x & 31;
    const int i    = blockIdx.x * 4 + wid;

    // deterministic per-warp neighbor list (4 rounds of 32 words, warp scans)
    int base_acc = 0;
#pragma unroll
    for (int r = 0; r < 4; r++) {
        uint32_t word = g_adj[i * ADJ_W + r * 32 + lane];
        int c = __popc(word);
        int sc = c;
#pragma unroll
        for (int off = 1; off < 32; off <<= 1) {
            int v = __shfl_up_sync(0xffffffffu, sc, off);
            if (lane >= off) sc += v;
        }
        int base  = base_acc + sc - c;
        int total = __shfl_sync(0xffffffffu, sc, 31);
        int hi = (r * 32 + lane) << 5;
        while (word) {
            int b = __ffs(word) - 1;
            word &= word - 1;
            lst[wid][base++] = (unsigned short)(hi + b);
        }
        base_acc += total;
    }
    __syncwarp();
    const int cnt = base_acc;
    const float ssrc = g_s2s[i];

    float mt = -1e30f;
    for (int n = lane; n < cnt; n += 32) mt = fmaxf(mt, g_s2t[(int)lst[wid][n]]);
#pragma unroll
    for (int off = 16; off; off >>= 1)
        mt = fmaxf(mt, __shfl_xor_sync(0xffffffffu, mt, off));
    float m = ssrc + mt;
    m = (m > 0.f) ? m : ALPHA_S * m;

    float acc[NCLASS];
#pragma unroll
    for (int k = 0; k < NCLASS; k++) acc[k] = 0.f;
    float Z = 0.f;

    if (cnt > 0) {
        for (int n = lane; n < cnt; n += 32) {
            int j = lst[wid][n];
            float e = ssrc + g_s2t[j];
            e = (e > 0.f) ? e : ALPHA_S * e;
            float w = __expf(e - m);
            Z += w;
            const float4* hp = (const float4*)&g_H2[j * NCLASS];
            float4 v0 = hp[0], v1 = hp[1], v2 = hp[2], v3 = hp[3];
            acc[0]  += w * v0.x; acc[1]  += w * v0.y; acc[2]  += w * v0.z; acc[3]  += w * v0.w;
            acc[4]  += w * v1.x; acc[5]  += w * v1.y; acc[6]  += w * v1.z; acc[7]  += w * v1.w;
            acc[8]  += w * v2.x; acc[9]  += w * v2.y; acc[10] += w * v2.z; acc[11] += w * v2.w;
            acc[12] += w * v3.x; acc[13] += w * v3.y; acc[14] += w * v3.z; acc[15] += w * v3.w;
        }
    } else {
        for (int j = lane; j < N_NODES; j += 32) {
            Z += 1.f;
            const float4* hp = (const float4*)&g_H2[j * NCLASS];
            float4 v0 = hp[0], v1 = hp[1], v2 = hp[2], v3 = hp[3];
            acc[0]  += v0.x; acc[1]  += v0.y; acc[2]  += v0.z; acc[3]  += v0.w;
            acc[4]  += v1.x; acc[5]  += v1.y; acc[6]  += v1.z; acc[7]  += v1.w;
            acc[8]  += v2.x; acc[9]  += v2.y; acc[10] += v2.z; acc[11] += v2.w;
            acc[12] += v3.x; acc[13] += v3.y; acc[14] += v3.z; acc[15] += v3.w;
        }
    }

#pragma unroll
    for (int off = 16; off; off >>= 1) {
        Z += __shfl_xor_sync(0xffffffffu, Z, off);
#pragma unroll
        for (int k = 0; k < NCLASS; k++)
            acc[k] += __shfl_xor_sync(0xffffffffu, acc[k], off);
    }

    if (lane == 0) {
        float invZ = 1.f / Z;
        float v[NCLASS];
        float mx = -1e30f;
#pragma unroll
        for (int k = 0; k < NCLASS; k++) {
            v[k] = acc[k] * invZ + b_out[k];
            mx = fmaxf(mx, v[k]);
        }
        float s = 0.f;
#pragma unroll
        for (int k = 0; k < NCLASS; k++) s += __expf(v[k] - mx);
        float ls = mx + logf(s);
#pragma unroll
        for (int k = 0; k < NCLASS; k++) out[i * NCLASS + k] = v[k] - ls;
    }
}

// ---------------- launch ------------------------------------------------------
extern "C" void kernel_launch(void* const* d_in, const int* in_sizes, int n_in,
                              void* d_out, int out_size) {
    const float* features = (const float*)d_in[0];
    const void*  edges    = d_in[1];
    const float* W_heads  = (const float*)d_in[2];
    const float* a_heads  = (const float*)d_in[3];
    const float* b_heads  = (const float*)d_in[4];
    const float* W_out    = (const float*)d_in[5];
    const float* a_out    = (const float*)d_in[6];
    const float* b_out    = (const float*)d_in[7];
    float* out = (float*)d_out;

    const int smem_g1 = 8 * TILEH * (int)sizeof(__half);   // 80 KB
    cudaFuncSetAttribute(k_gemm1_tc, cudaFuncAttributeMaxDynamicSharedMemorySize, smem_g1);

    void* adj_ptr = nullptr;
    cudaGetSymbolAddress(&adj_ptr, g_adj);
    cudaMemsetAsync(adj_ptr, 0, N_NODES * ADJ_W * sizeof(uint32_t), 0);

    k_detect<<<1, 1>>>((const uint32_t*)edges);
    k_scatter<<<N_EDGES / 256, 256>>>(edges);
    k_prep<<<1280, 1024>>>(features, W_heads);
    {
        dim3 g(HTOT / 128, N_NODES / 128);
        k_gemm1_tc<<<g, 512, smem_g1>>>(a_heads);
    }
    k_agg1<<<N_NODES, 128>>>(b_heads);
    k_gemm2<<<N_NODES / 16, 256>>>(W_out, a_out);
    k_agg2<<<N_NODES / 4, 128>>>(b_out, out);
}